// round 6
// baseline (speedup 1.0000x reference)
#include <cuda_runtime.h>
#include <cstdint>

#define T_TOK    16384
#define DIM      2048
#define NEXP     64
#define NB       4
#define SEQ      4096
#define BM       64
#define BK       32
#define NCHUNK   (DIM / BK)      // 64
#define NTHREADS 256

// smem layout (floats), per stage
#define A_ROW    36              // 32 + 4 pad
#define B_ROW    68              // 64 + 4 pad
#define AS_OFF   0
#define BH_OFF   (BM * A_ROW)                 // 2304
#define BL_OFF   (BH_OFF + BK * B_ROW)        // 4480
#define STAGE_F  (BL_OFF + BK * B_ROW)        // 6656 floats = 26624 B
#define SMEM_BYTES (2 * STAGE_F * 4)          // 53248 B

__device__ float        g_score_sum[NB * NEXP];   // zeroed at load; finalize re-zeros
__device__ unsigned int g_counts[NB * NEXP];

__device__ __forceinline__ void split_tf32(float x, uint32_t& h, uint32_t& l) {
    asm("cvt.rna.tf32.f32 %0, %1;" : "=r"(h) : "f"(x));
    float r = x - __uint_as_float(h);
    asm("cvt.rna.tf32.f32 %0, %1;" : "=r"(l) : "f"(r));
}

__device__ __forceinline__ void mma_tf32(float* c,
                                         uint32_t a0, uint32_t a1, uint32_t a2, uint32_t a3,
                                         uint32_t b0, uint32_t b1) {
    asm volatile(
        "mma.sync.aligned.m16n8k8.row.col.f32.tf32.tf32.f32 "
        "{%0,%1,%2,%3}, {%4,%5,%6,%7}, {%8,%9}, {%0,%1,%2,%3};"
        : "+f"(c[0]), "+f"(c[1]), "+f"(c[2]), "+f"(c[3])
        : "r"(a0), "r"(a1), "r"(a2), "r"(a3), "r"(b0), "r"(b1));
}

__global__ __launch_bounds__(NTHREADS, 2)
void moe_gate_mma(const float* __restrict__ X,
                  const float* __restrict__ W,
                  float* __restrict__ out)
{
    extern __shared__ float sm[];
    __shared__ unsigned int cnt[NEXP];

    const int tid  = threadIdx.x;
    const int wid  = tid >> 5;
    const int lane = tid & 31;
    const int g    = lane >> 2;      // group id 0..7
    const int tg   = lane & 3;       // thread-in-group 0..3
    const int wm   = (wid >> 1) * 16;   // warp token base
    const int wn   = (wid & 1) * 32;    // warp expert base
    const int tok0 = blockIdx.x * BM;

    // load geometry: thread t handles row = t>>2, cols (t&3)*8 .. +7 (two float4)
    const int lrow = tid >> 2;
    const int lcol = (tid & 3) * 8;

    // acc_h: hi*hi stream; acc_l: hi*lo + lo*hi + lo*lo stream (small terms)
    float acc_h[4][4], acc_l[4][4];
#pragma unroll
    for (int nt = 0; nt < 4; nt++)
#pragma unroll
        for (int i = 0; i < 4; i++) { acc_h[nt][i] = 0.0f; acc_l[nt][i] = 0.0f; }

    float4 ra0, ra1, rw0, rw1;

    // ---- prolog: load chunk 0 ----
    ra0 = *(const float4*)&X[(size_t)(tok0 + lrow) * DIM + lcol];
    ra1 = *(const float4*)&X[(size_t)(tok0 + lrow) * DIM + lcol + 4];
    rw0 = *(const float4*)&W[(size_t)lrow * DIM + lcol];
    rw1 = *(const float4*)&W[(size_t)lrow * DIM + lcol + 4];

    // store chunk 0 into stage 0
    {
        float* As = sm + AS_OFF;
        float* Bh = sm + BH_OFF;
        float* Bl = sm + BL_OFF;
        *(float4*)&As[lrow * A_ROW + lcol]     = ra0;
        *(float4*)&As[lrow * A_ROW + lcol + 4] = ra1;
        float wv[8] = { rw0.x, rw0.y, rw0.z, rw0.w, rw1.x, rw1.y, rw1.z, rw1.w };
#pragma unroll
        for (int j = 0; j < 8; j++) {
            uint32_t h, l;
            split_tf32(wv[j], h, l);
            Bh[(lcol + j) * B_ROW + lrow] = __uint_as_float(h);
            Bl[(lcol + j) * B_ROW + lrow] = __uint_as_float(l);
        }
    }
    __syncthreads();

    for (int kt = 0; kt < NCHUNK; kt++) {
        const int stage = kt & 1;

        // ---- prefetch next chunk into regs ----
        if (kt + 1 < NCHUNK) {
            const int k0 = (kt + 1) * BK;
            ra0 = *(const float4*)&X[(size_t)(tok0 + lrow) * DIM + k0 + lcol];
            ra1 = *(const float4*)&X[(size_t)(tok0 + lrow) * DIM + k0 + lcol + 4];
            rw0 = *(const float4*)&W[(size_t)lrow * DIM + k0 + lcol];
            rw1 = *(const float4*)&W[(size_t)lrow * DIM + k0 + lcol + 4];
        }

        // ---- compute on current stage: 4 k8-steps ----
        {
            const float* As = sm + stage * STAGE_F + AS_OFF;
            const float* Bh = sm + stage * STAGE_F + BH_OFF;
            const float* Bl = sm + stage * STAGE_F + BL_OFF;
#pragma unroll
            for (int s = 0; s < 4; s++) {
                const int kb = s * 8;
                const float* Ap = As + (wm + g) * A_ROW + kb + tg;
                float a0f = Ap[0];
                float a1f = Ap[8 * A_ROW];
                float a2f = Ap[4];
                float a3f = Ap[8 * A_ROW + 4];

                uint32_t bh0[4], bh1[4], bl0[4], bl1[4];
#pragma unroll
                for (int nt = 0; nt < 4; nt++) {
                    const int e = wn + nt * 8 + g;
                    bh0[nt] = __float_as_uint(Bh[(kb + tg) * B_ROW + e]);
                    bh1[nt] = __float_as_uint(Bh[(kb + tg + 4) * B_ROW + e]);
                    bl0[nt] = __float_as_uint(Bl[(kb + tg) * B_ROW + e]);
                    bl1[nt] = __float_as_uint(Bl[(kb + tg + 4) * B_ROW + e]);
                }

                uint32_t ah0, al0, ah1, al1, ah2, al2, ah3, al3;
                split_tf32(a0f, ah0, al0);
                split_tf32(a1f, ah1, al1);
                split_tf32(a2f, ah2, al2);
                split_tf32(a3f, ah3, al3);

#pragma unroll
                for (int nt = 0; nt < 4; nt++) {
                    mma_tf32(acc_h[nt], ah0, ah1, ah2, ah3, bh0[nt], bh1[nt]);
                    mma_tf32(acc_l[nt], ah0, ah1, ah2, ah3, bl0[nt], bl1[nt]);
                    mma_tf32(acc_l[nt], al0, al1, al2, al3, bh0[nt], bh1[nt]);
                    mma_tf32(acc_l[nt], al0, al1, al2, al3, bl0[nt], bl1[nt]);
                }
            }
        }

        // ---- store prefetched regs into other stage ----
        if (kt + 1 < NCHUNK) {
            float* As = sm + (stage ^ 1) * STAGE_F + AS_OFF;
            float* Bh = sm + (stage ^ 1) * STAGE_F + BH_OFF;
            float* Bl = sm + (stage ^ 1) * STAGE_F + BL_OFF;
            *(float4*)&As[lrow * A_ROW + lcol]     = ra0;
            *(float4*)&As[lrow * A_ROW + lcol + 4] = ra1;
            float wv[8] = { rw0.x, rw0.y, rw0.z, rw0.w, rw1.x, rw1.y, rw1.z, rw1.w };
#pragma unroll
            for (int j = 0; j < 8; j++) {
                uint32_t h, l;
                split_tf32(wv[j], h, l);
                Bh[(lcol + j) * B_ROW + lrow] = __uint_as_float(h);
                Bl[(lcol + j) * B_ROW + lrow] = __uint_as_float(l);
            }
        }
        __syncthreads();
    }

    // ---- writeback C fragments (hi + small-term streams) to smem scores ----
    float* sc = sm;   // reuse stage 0 region: 64*68 floats
#pragma unroll
    for (int nt = 0; nt < 4; nt++) {
        const int e = wn + nt * 8 + 2 * tg;
        *(float2*)&sc[(wm + g) * B_ROW + e] =
            make_float2(acc_h[nt][0] + acc_l[nt][0], acc_h[nt][1] + acc_l[nt][1]);
        *(float2*)&sc[(wm + g + 8) * B_ROW + e] =
            make_float2(acc_h[nt][2] + acc_l[nt][2], acc_h[nt][3] + acc_l[nt][3]);
    }
    if (tid < NEXP) cnt[tid] = 0u;
    __syncthreads();

    // ---- per-token softmax + top-2 (one thread per token) ----
    if (tid < BM) {
        float v[64];
#pragma unroll
        for (int e = 0; e < NEXP; e++) v[e] = sc[tid * B_ROW + e];
        float mx = v[0];
#pragma unroll
        for (int e = 1; e < NEXP; e++) mx = fmaxf(mx, v[e]);
        float sum = 0.0f;
#pragma unroll
        for (int e = 0; e < NEXP; e++) { v[e] = expf(v[e] - mx); sum += v[e]; }
        float inv = 1.0f / sum;

        float v1 = -1.0f, v2 = -1.0f;
        int i1 = 0, i2 = 0;
#pragma unroll
        for (int e = 0; e < NEXP; e++) {
            float p = v[e] * inv;
            sc[tid * B_ROW + e] = p;            // softmax score (for aux sums)
            if (p > v1) { v2 = v1; i2 = i1; v1 = p; i1 = e; }
            else if (p > v2) { v2 = p; i2 = e; }
        }
        float tot = v1 + v2 + 1e-20f;
        int gt = tok0 + tid;
        out[2 * gt + 0] = (float)i1;
        out[2 * gt + 1] = (float)i2;
        out[2 * T_TOK + 2 * gt + 0] = v1 / tot;
        out[2 * T_TOK + 2 * gt + 1] = v2 / tot;

        atomicAdd(&cnt[i1], 1u);
        atomicAdd(&cnt[i2], 1u);
    }
    __syncthreads();

    // ---- per-expert column sums + count flush ----
    if (tid < NEXP) {
        float cs = 0.0f;
#pragma unroll 8
        for (int t = 0; t < BM; t++) cs += sc[t * B_ROW + tid];
        int b = tok0 / SEQ;
        atomicAdd(&g_score_sum[b * NEXP + tid], cs);
        atomicAdd(&g_counts[b * NEXP + tid], cnt[tid]);
    }
}

__global__ void finalize_aux_kernel(float* __restrict__ out_aux) {
    __shared__ float red[NB * NEXP];
    int i = threadIdx.x;   // 256 = NB*NEXP
    float v = (float)g_counts[i] * ((float)NEXP / (float)(SEQ * 2))
              * (g_score_sum[i] / (float)SEQ);
    g_score_sum[i] = 0.0f;
    g_counts[i] = 0u;
    red[i] = v;
    __syncthreads();
    for (int s = (NB * NEXP) / 2; s > 0; s >>= 1) {
        if (i < s) red[i] += red[i + s];
        __syncthreads();
    }
    if (i == 0) out_aux[0] = red[0] * (0.1f / (float)NB);
}

extern "C" void kernel_launch(void* const* d_in, const int* in_sizes, int n_in,
                              void* d_out, int out_size) {
    const float* X = (const float*)d_in[0];   // [4,4096,2048] f32
    const float* W = (const float*)d_in[1];   // [64,2048] f32
    float* out = (float*)d_out;

    cudaFuncSetAttribute(moe_gate_mma, cudaFuncAttributeMaxDynamicSharedMemorySize, SMEM_BYTES);
    moe_gate_mma<<<T_TOK / BM, NTHREADS, SMEM_BYTES>>>(X, W, out);
    finalize_aux_kernel<<<1, 256>>>(out + 4 * T_TOK);
}